// round 2
// baseline (speedup 1.0000x reference)
#include <cuda_runtime.h>
#include <cstdint>

// ---------------------------------------------------------------------------
// SpecAugment on GB300 — R2: MLP-batched streaming apply.
// Threefry2x32 (JAX partitionable path) reproduced bit-exactly for masks,
// then a pure one-pass multiply-by-{0,1} stream at 4 float4 per thread.
// B=128, T=4000, F=128.
// ---------------------------------------------------------------------------

#define FREQ_MASK_SIZE 27.0f
#define TIME_MASK_PCT  0.25f

__device__ float g_fmul[128];   // per-frequency-bin multiplier (0.0 or 1.0)
__device__ int4  g_trange[128]; // per-batch time-mask intervals [x,y) U [z,w)

// ---- Threefry2x32 (20 rounds), identical to jax._src.prng.threefry2x32 ----
__device__ __forceinline__ uint2 threefry2x32(unsigned k0, unsigned k1,
                                              unsigned x0, unsigned x1) {
    unsigned ks2 = k0 ^ k1 ^ 0x1BD11BDAu;
    x0 += k0; x1 += k1;
#define TF_RND(r) { x0 += x1; x1 = __funnelshift_l(x1, x1, (r)); x1 ^= x0; }
    TF_RND(13) TF_RND(15) TF_RND(26) TF_RND(6)
    x0 += k1;  x1 += ks2 + 1u;
    TF_RND(17) TF_RND(29) TF_RND(16) TF_RND(24)
    x0 += ks2; x1 += k0 + 2u;
    TF_RND(13) TF_RND(15) TF_RND(26) TF_RND(6)
    x0 += k0;  x1 += k1 + 3u;
    TF_RND(17) TF_RND(29) TF_RND(16) TF_RND(24)
    x0 += k1;  x1 += ks2 + 4u;
    TF_RND(13) TF_RND(15) TF_RND(26) TF_RND(6)
    x0 += ks2; x1 += k0 + 5u;
#undef TF_RND
    return make_uint2(x0, x1);
}

__device__ __forceinline__ unsigned rbits32(uint2 k, unsigned j) {
    uint2 h = threefry2x32(k.x, k.y, 0u, j);
    return h.x ^ h.y;
}

__device__ __forceinline__ float bits_to_unit(unsigned bits) {
    return __uint_as_float((bits >> 9) | 0x3F800000u) - 1.0f;
}

// ---------------------------------------------------------------------------
// Setup: one block of 128 threads; thread i is frequency bin i AND batch i.
// ---------------------------------------------------------------------------
__global__ void specaug_setup_kernel(const int* __restrict__ x_len,
                                     int B, int F) {
    const int i = threadIdx.x;

    const uint2 kf = threefry2x32(0u, 42u, 0u, 0u);
    const uint2 kv = threefry2x32(0u, 42u, 0u, 1u);
    const uint2 ks = threefry2x32(0u, 42u, 0u, 2u);

    // frequency masks (shared across batch)
    float u00 = bits_to_unit(rbits32(kf, 0u));
    float u01 = bits_to_unit(rbits32(kf, 1u));
    float u10 = bits_to_unit(rbits32(kf, 2u));
    float u11 = bits_to_unit(rbits32(kf, 3u));

    float Ff = (float)F;
    float fv0 = __fmul_rn(u00, FREQ_MASK_SIZE);
    float fb0 = __fmul_rn(u01, __fsub_rn(Ff, fv0));
    float fs0 = floorf(fb0);
    float fe0 = floorf(__fadd_rn(fb0, fv0));
    float fv1 = __fmul_rn(u10, FREQ_MASK_SIZE);
    float fb1 = __fmul_rn(u11, __fsub_rn(Ff, fv1));
    float fs1 = floorf(fb1);
    float fe1 = floorf(__fadd_rn(fb1, fv1));

    if (i < F) {
        float ff = (float)i;
        bool fm = (ff >= fs0 && ff < fe0) || (ff >= fs1 && ff < fe1);
        g_fmul[i] = fm ? 0.0f : 1.0f;
    }

    // per-batch adaptive time masks
    if (i < B) {
        float xl = (float)x_len[i];
        float tparam = floorf(__fmul_rn(TIME_MASK_PCT, xl));

        float uv0 = bits_to_unit(rbits32(kv, 2u * i));
        float uv1 = bits_to_unit(rbits32(kv, 2u * i + 1u));
        float us0 = bits_to_unit(rbits32(ks, 2u * i));
        float us1 = bits_to_unit(rbits32(ks, 2u * i + 1u));

        float tv0 = __fmul_rn(uv0, tparam);
        float tb0 = __fmul_rn(us0, __fsub_rn(xl, tv0));
        int   ts0 = (int)floorf(tb0);
        int   te0 = (int)floorf(__fadd_rn(tb0, tv0));

        float tv1 = __fmul_rn(uv1, tparam);
        float tb1 = __fmul_rn(us1, __fsub_rn(xl, tv1));
        int   ts1 = (int)floorf(tb1);
        int   te1 = (int)floorf(__fadd_rn(tb1, tv1));

        g_trange[i] = make_int4(ts0, te0, ts1, te1);
    }
}

// ---------------------------------------------------------------------------
// Streaming apply — 4 float4 per thread (4 consecutive t-rows, same b/q).
// Block = 256 threads covers 32 t-rows; grid = (T/32, B). T=4000 -> exact.
// ---------------------------------------------------------------------------
__global__ void __launch_bounds__(256)
specaug_apply_kernel(const float4* __restrict__ x,
                     float4* __restrict__ out,
                     int T) {
    const int b  = blockIdx.y;
    const int t0 = blockIdx.x * 32 + (threadIdx.x >> 5) * 4;
    const int q  = threadIdx.x & 31;

    const size_t base = ((size_t)b * T + t0) * 32 + q;

    // Front-batched streaming loads: MLP_p1 = 4.
    float4 v0 = __ldcs(x + base);
    float4 v1 = __ldcs(x + base + 32);
    float4 v2 = __ldcs(x + base + 64);
    float4 v3 = __ldcs(x + base + 96);

    const int4  tr = g_trange[b];
    const float4 fm = reinterpret_cast<const float4*>(g_fmul)[q];

    #pragma unroll
    for (int i = 0; i < 4; i++) {
        const int t = t0 + i;
        const bool tmask = (t >= tr.x && t < tr.y) || (t >= tr.z && t < tr.w);
        float4 v = (i == 0) ? v0 : (i == 1) ? v1 : (i == 2) ? v2 : v3;
        float4 r;
        if (tmask) {
            r = make_float4(0.f, 0.f, 0.f, 0.f);
        } else {
            r.x = v.x * fm.x;
            r.y = v.y * fm.y;
            r.z = v.z * fm.z;
            r.w = v.w * fm.w;
        }
        __stcs(out + base + (size_t)i * 32, r);
    }
}

extern "C" void kernel_launch(void* const* d_in, const int* in_sizes, int n_in,
                              void* d_out, int out_size) {
    const float* x     = (const float*)d_in[0];
    const int*   x_len = (const int*)d_in[1];
    float*       out   = (float*)d_out;

    const int B = in_sizes[1];                 // 128
    const int F = 128;                         // fixed by problem shape
    const int T = in_sizes[0] / (B * F);       // 4000

    specaug_setup_kernel<<<1, 128>>>(x_len, B, F);

    dim3 grid(T / 32, B);                      // 125 x 128 blocks
    specaug_apply_kernel<<<grid, 256>>>(
        (const float4*)x, (float4*)out, T);
    (void)n_in; (void)out_size;
}

// round 3
// speedup vs baseline: 1.0858x; 1.0858x over previous
#include <cuda_runtime.h>
#include <cstdint>

// ---------------------------------------------------------------------------
// SpecAugment on GB300 — R3: single fused kernel.
//  * Subkeys of jax.random.split(key(42),3) baked in at compile time
//    (constexpr threefry2x32).
//  * 8 runtime threefry hashes per warp, computed SIMT-parallel across
//    lanes 0..7 and shfl-broadcast — no setup kernel, no scratch globals.
//  * Reads skipped where the output is provably zero (time-masked rows are
//    warp-uniform; fully freq-masked float4 lanes are predicated off).
// B=128, T=4000, F=128.
// ---------------------------------------------------------------------------

#define FREQ_MASK_SIZE 27.0f
#define TIME_MASK_PCT  0.25f

// ---- constexpr Threefry2x32 (20 rounds) for compile-time subkeys ----------
struct TFPair { unsigned a, b; };

constexpr unsigned rotl32c(unsigned x, int r) {
    return (x << r) | (x >> (32 - r));
}

constexpr TFPair threefry_const(unsigned k0, unsigned k1,
                                unsigned x0, unsigned x1) {
    unsigned ks2 = k0 ^ k1 ^ 0x1BD11BDAu;
    x0 += k0; x1 += k1;
    const int R[8] = {13, 15, 26, 6, 17, 29, 16, 24};
    // 5 groups of 4 rounds, with key injections between groups
    for (int g = 0; g < 5; g++) {
        const int* r = (g % 2 == 0) ? R : R + 4;
        for (int i = 0; i < 4; i++) {
            x0 += x1; x1 = rotl32c(x1, r[i]); x1 ^= x0;
        }
        switch (g) {
            case 0: x0 += k1;  x1 += ks2 + 1u; break;
            case 1: x0 += ks2; x1 += k0 + 2u;  break;
            case 2: x0 += k0;  x1 += k1 + 3u;  break;
            case 3: x0 += k1;  x1 += ks2 + 4u; break;
            case 4: x0 += ks2; x1 += k0 + 5u;  break;
        }
    }
    return TFPair{x0, x1};
}

// split(key(42), 3), partitionable path: child i = threefry(key, (0, i))
constexpr TFPair KF = threefry_const(0u, 42u, 0u, 0u);
constexpr TFPair KV = threefry_const(0u, 42u, 0u, 1u);
constexpr TFPair KS = threefry_const(0u, 42u, 0u, 2u);

// ---- device Threefry2x32 (same schedule, funnel-shift rotates) ------------
__device__ __forceinline__ uint2 threefry2x32(unsigned k0, unsigned k1,
                                              unsigned x0, unsigned x1) {
    unsigned ks2 = k0 ^ k1 ^ 0x1BD11BDAu;
    x0 += k0; x1 += k1;
#define TF_RND(r) { x0 += x1; x1 = __funnelshift_l(x1, x1, (r)); x1 ^= x0; }
    TF_RND(13) TF_RND(15) TF_RND(26) TF_RND(6)
    x0 += k1;  x1 += ks2 + 1u;
    TF_RND(17) TF_RND(29) TF_RND(16) TF_RND(24)
    x0 += ks2; x1 += k0 + 2u;
    TF_RND(13) TF_RND(15) TF_RND(26) TF_RND(6)
    x0 += k0;  x1 += k1 + 3u;
    TF_RND(17) TF_RND(29) TF_RND(16) TF_RND(24)
    x0 += k1;  x1 += ks2 + 4u;
    TF_RND(13) TF_RND(15) TF_RND(26) TF_RND(6)
    x0 += ks2; x1 += k0 + 5u;
#undef TF_RND
    return make_uint2(x0, x1);
}

__device__ __forceinline__ float bits_to_unit(unsigned bits) {
    return __uint_as_float((bits >> 9) | 0x3F800000u) - 1.0f;
}

// ---------------------------------------------------------------------------
// Fused kernel. Block = 256 threads = 8 warps; warp = 32 float4 lanes (q)
// over 4 consecutive t-rows. Grid = (T/32, B).
// ---------------------------------------------------------------------------
__global__ void __launch_bounds__(256)
specaug_fused_kernel(const float4* __restrict__ x,
                     float4* __restrict__ out,
                     const int* __restrict__ x_len,
                     int T) {
    const int b  = blockIdx.y;
    const int t0 = blockIdx.x * 32 + (threadIdx.x >> 5) * 4;
    const int q  = threadIdx.x & 31;

    // ---- 8 mask hashes, SIMT-parallel across lanes 0..7 -------------------
    const unsigned sel = (unsigned)q & 7u;
    unsigned k0, k1, j;
    if (sel < 4u)      { k0 = KF.a; k1 = KF.b; j = sel; }
    else if (sel < 6u) { k0 = KV.a; k1 = KV.b; j = 2u * (unsigned)b + (sel - 4u); }
    else               { k0 = KS.a; k1 = KS.b; j = 2u * (unsigned)b + (sel - 6u); }
    uint2 h = threefry2x32(k0, k1, 0u, j);
    float u = bits_to_unit(h.x ^ h.y);

    const unsigned FULL = 0xFFFFFFFFu;
    float u00 = __shfl_sync(FULL, u, 0);   // uf[0,0]
    float u01 = __shfl_sync(FULL, u, 1);   // uf[0,1]
    float u10 = __shfl_sync(FULL, u, 2);   // uf[1,0]
    float u11 = __shfl_sync(FULL, u, 3);   // uf[1,1]
    float uv0 = __shfl_sync(FULL, u, 4);   // uv[b,0]
    float uv1 = __shfl_sync(FULL, u, 5);   // uv[b,1]
    float us0 = __shfl_sync(FULL, u, 6);   // us[b,0]
    float us1 = __shfl_sync(FULL, u, 7);   // us[b,1]

    // ---- frequency-mask intervals (fp32, matching reference exactly) ------
    const float Ff = 128.0f;
    float fv0 = __fmul_rn(u00, FREQ_MASK_SIZE);
    float fb0 = __fmul_rn(u01, __fsub_rn(Ff, fv0));
    float fs0 = floorf(fb0);
    float fe0 = floorf(__fadd_rn(fb0, fv0));
    float fv1 = __fmul_rn(u10, FREQ_MASK_SIZE);
    float fb1 = __fmul_rn(u11, __fsub_rn(Ff, fv1));
    float fs1 = floorf(fb1);
    float fe1 = floorf(__fadd_rn(fb1, fv1));

    // ---- adaptive time-mask intervals for batch b --------------------------
    float xl = (float)__ldg(x_len + b);
    float tparam = floorf(__fmul_rn(TIME_MASK_PCT, xl));

    float tv0 = __fmul_rn(uv0, tparam);
    float tb0 = __fmul_rn(us0, __fsub_rn(xl, tv0));
    int   ts0 = (int)floorf(tb0);
    int   te0 = (int)floorf(__fadd_rn(tb0, tv0));
    float tv1 = __fmul_rn(uv1, tparam);
    float tb1 = __fmul_rn(us1, __fsub_rn(xl, tv1));
    int   ts1 = (int)floorf(tb1);
    int   te1 = (int)floorf(__fadd_rn(tb1, tv1));

    // ---- per-lane frequency multiplier for bins 4q..4q+3 -------------------
    float4 fm;
    {
        float f0 = (float)(4 * q);
        float f1 = f0 + 1.0f, f2 = f0 + 2.0f, f3 = f0 + 3.0f;
        fm.x = ((f0 >= fs0 && f0 < fe0) || (f0 >= fs1 && f0 < fe1)) ? 0.f : 1.f;
        fm.y = ((f1 >= fs0 && f1 < fe0) || (f1 >= fs1 && f1 < fe1)) ? 0.f : 1.f;
        fm.z = ((f2 >= fs0 && f2 < fe0) || (f2 >= fs1 && f2 < fe1)) ? 0.f : 1.f;
        fm.w = ((f3 >= fs0 && f3 < fe0) || (f3 >= fs1 && f3 < fe1)) ? 0.f : 1.f;
    }
    const bool fmzero = (fm.x + fm.y + fm.z + fm.w) == 0.f;

    // ---- streaming apply: predicated loads, mandatory stores ---------------
    const size_t base = ((size_t)b * T + t0) * 32 + q;

    bool p[4];
    #pragma unroll
    for (int i = 0; i < 4; i++) {
        const int t = t0 + i;
        const bool tmask = (t >= ts0 && t < te0) || (t >= ts1 && t < te1);
        p[i] = !(tmask || fmzero);
    }

    float4 v[4];
    #pragma unroll
    for (int i = 0; i < 4; i++) {
        v[i] = make_float4(0.f, 0.f, 0.f, 0.f);
        if (p[i]) v[i] = __ldcs(x + base + (size_t)i * 32);
    }

    #pragma unroll
    for (int i = 0; i < 4; i++) {
        float4 r;
        if (p[i]) {
            r.x = v[i].x * fm.x;
            r.y = v[i].y * fm.y;
            r.z = v[i].z * fm.z;
            r.w = v[i].w * fm.w;
        } else {
            r = make_float4(0.f, 0.f, 0.f, 0.f);
        }
        __stcs(out + base + (size_t)i * 32, r);
    }
}

extern "C" void kernel_launch(void* const* d_in, const int* in_sizes, int n_in,
                              void* d_out, int out_size) {
    const float* x     = (const float*)d_in[0];
    const int*   x_len = (const int*)d_in[1];
    float*       out   = (float*)d_out;

    const int B = in_sizes[1];                 // 128
    const int F = 128;                         // fixed by problem shape
    const int T = in_sizes[0] / (B * F);       // 4000

    dim3 grid(T / 32, B);                      // 125 x 128 blocks, one node
    specaug_fused_kernel<<<grid, 256>>>(
        (const float4*)x, (float4*)out, x_len, T);
    (void)n_in; (void)out_size; (void)F;
}

// round 4
// speedup vs baseline: 1.0862x; 1.0004x over previous
#include <cuda_runtime.h>
#include <cstdint>

// ---------------------------------------------------------------------------
// SpecAugment on GB300 — R4: fused kernel, hash amortized.
//  * Subkeys of jax.random.split(key(42),3) constexpr-baked.
//  * Warp 0 computes the 8 threefry hashes (SIMT over lanes 0..7) and the
//    mask intervals once per block; smem broadcast to the other warps.
//  * 8 float4 per thread (MLP_p1=8), streaming ld/st, reads predicated off
//    where output is provably zero.
// B=128, T=4000, F=128.  Block=128thr covers 32 t-rows; grid=(125,128).
// ---------------------------------------------------------------------------

#define FREQ_MASK_SIZE 27.0f
#define TIME_MASK_PCT  0.25f

// ---- constexpr Threefry2x32 (20 rounds) for compile-time subkeys ----------
struct TFPair { unsigned a, b; };

constexpr unsigned rotl32c(unsigned x, int r) {
    return (x << r) | (x >> (32 - r));
}

constexpr TFPair threefry_const(unsigned k0, unsigned k1,
                                unsigned x0, unsigned x1) {
    unsigned ks2 = k0 ^ k1 ^ 0x1BD11BDAu;
    x0 += k0; x1 += k1;
    const int R[8] = {13, 15, 26, 6, 17, 29, 16, 24};
    for (int g = 0; g < 5; g++) {
        const int* r = (g % 2 == 0) ? R : R + 4;
        for (int i = 0; i < 4; i++) {
            x0 += x1; x1 = rotl32c(x1, r[i]); x1 ^= x0;
        }
        switch (g) {
            case 0: x0 += k1;  x1 += ks2 + 1u; break;
            case 1: x0 += ks2; x1 += k0 + 2u;  break;
            case 2: x0 += k0;  x1 += k1 + 3u;  break;
            case 3: x0 += k1;  x1 += ks2 + 4u; break;
            case 4: x0 += ks2; x1 += k0 + 5u;  break;
        }
    }
    return TFPair{x0, x1};
}

// split(key(42), 3), partitionable path: child i = threefry(key, (0, i))
constexpr TFPair KF = threefry_const(0u, 42u, 0u, 0u);
constexpr TFPair KV = threefry_const(0u, 42u, 0u, 1u);
constexpr TFPair KS = threefry_const(0u, 42u, 0u, 2u);

// ---- device Threefry2x32 (same schedule) ----------------------------------
__device__ __forceinline__ uint2 threefry2x32(unsigned k0, unsigned k1,
                                              unsigned x0, unsigned x1) {
    unsigned ks2 = k0 ^ k1 ^ 0x1BD11BDAu;
    x0 += k0; x1 += k1;
#define TF_RND(r) { x0 += x1; x1 = __funnelshift_l(x1, x1, (r)); x1 ^= x0; }
    TF_RND(13) TF_RND(15) TF_RND(26) TF_RND(6)
    x0 += k1;  x1 += ks2 + 1u;
    TF_RND(17) TF_RND(29) TF_RND(16) TF_RND(24)
    x0 += ks2; x1 += k0 + 2u;
    TF_RND(13) TF_RND(15) TF_RND(26) TF_RND(6)
    x0 += k0;  x1 += k1 + 3u;
    TF_RND(17) TF_RND(29) TF_RND(16) TF_RND(24)
    x0 += k1;  x1 += ks2 + 4u;
    TF_RND(13) TF_RND(15) TF_RND(26) TF_RND(6)
    x0 += ks2; x1 += k0 + 5u;
#undef TF_RND
    return make_uint2(x0, x1);
}

__device__ __forceinline__ float bits_to_unit(unsigned bits) {
    return __uint_as_float((bits >> 9) | 0x3F800000u) - 1.0f;
}

// ---------------------------------------------------------------------------
// Fused kernel. Block = 128 threads = 4 warps; warp w handles t-rows
// [t0, t0+8) with 32 float4 lanes over F=128. Grid = (T/32, B).
// ---------------------------------------------------------------------------
__global__ void __launch_bounds__(128)
specaug_fused_kernel(const float4* __restrict__ x,
                     float4* __restrict__ out,
                     const int* __restrict__ x_len,
                     int T) {
    __shared__ float s_f[4];   // fs0, fe0, fs1, fe1
    __shared__ int   s_t[4];   // ts0, te0, ts1, te1

    const int b = blockIdx.y;
    const int w = threadIdx.x >> 5;
    const int q = threadIdx.x & 31;

    // ---- warp 0: hashes + mask intervals, once per block -------------------
    if (w == 0) {
        const unsigned sel = (unsigned)q & 7u;
        unsigned k0, k1, j;
        if (sel < 4u)      { k0 = KF.a; k1 = KF.b; j = sel; }
        else if (sel < 6u) { k0 = KV.a; k1 = KV.b; j = 2u * (unsigned)b + (sel - 4u); }
        else               { k0 = KS.a; k1 = KS.b; j = 2u * (unsigned)b + (sel - 6u); }
        uint2 h = threefry2x32(k0, k1, 0u, j);
        float u = bits_to_unit(h.x ^ h.y);

        const unsigned FULL = 0xFFFFFFFFu;
        float u00 = __shfl_sync(FULL, u, 0);
        float u01 = __shfl_sync(FULL, u, 1);
        float u10 = __shfl_sync(FULL, u, 2);
        float u11 = __shfl_sync(FULL, u, 3);
        float uv0 = __shfl_sync(FULL, u, 4);
        float uv1 = __shfl_sync(FULL, u, 5);
        float us0 = __shfl_sync(FULL, u, 6);
        float us1 = __shfl_sync(FULL, u, 7);

        if (q == 0) {
            // frequency masks (fp32 ops matching the reference exactly)
            const float Ff = 128.0f;
            float fv0 = __fmul_rn(u00, FREQ_MASK_SIZE);
            float fb0 = __fmul_rn(u01, __fsub_rn(Ff, fv0));
            s_f[0] = floorf(fb0);
            s_f[1] = floorf(__fadd_rn(fb0, fv0));
            float fv1 = __fmul_rn(u10, FREQ_MASK_SIZE);
            float fb1 = __fmul_rn(u11, __fsub_rn(Ff, fv1));
            s_f[2] = floorf(fb1);
            s_f[3] = floorf(__fadd_rn(fb1, fv1));

            // adaptive time masks for batch b
            float xl = (float)__ldg(x_len + b);
            float tparam = floorf(__fmul_rn(TIME_MASK_PCT, xl));

            float tv0 = __fmul_rn(uv0, tparam);
            float tb0 = __fmul_rn(us0, __fsub_rn(xl, tv0));
            s_t[0] = (int)floorf(tb0);
            s_t[1] = (int)floorf(__fadd_rn(tb0, tv0));
            float tv1 = __fmul_rn(uv1, tparam);
            float tb1 = __fmul_rn(us1, __fsub_rn(xl, tv1));
            s_t[2] = (int)floorf(tb1);
            s_t[3] = (int)floorf(__fadd_rn(tb1, tv1));
        }
    }
    __syncthreads();

    const float fs0 = s_f[0], fe0 = s_f[1], fs1 = s_f[2], fe1 = s_f[3];
    const int   ts0 = s_t[0], te0 = s_t[1], ts1 = s_t[2], te1 = s_t[3];

    // ---- per-lane frequency multiplier for bins 4q..4q+3 -------------------
    float4 fm;
    {
        float f0 = (float)(4 * q);
        float f1 = f0 + 1.0f, f2 = f0 + 2.0f, f3 = f0 + 3.0f;
        fm.x = ((f0 >= fs0 && f0 < fe0) || (f0 >= fs1 && f0 < fe1)) ? 0.f : 1.f;
        fm.y = ((f1 >= fs0 && f1 < fe0) || (f1 >= fs1 && f1 < fe1)) ? 0.f : 1.f;
        fm.z = ((f2 >= fs0 && f2 < fe0) || (f2 >= fs1 && f2 < fe1)) ? 0.f : 1.f;
        fm.w = ((f3 >= fs0 && f3 < fe0) || (f3 >= fs1 && f3 < fe1)) ? 0.f : 1.f;
    }
    const bool fmzero = (fm.x + fm.y + fm.z + fm.w) == 0.f;

    // ---- streaming apply: 8 rows per thread --------------------------------
    const int t0 = blockIdx.x * 32 + w * 8;
    const size_t base = ((size_t)b * T + t0) * 32 + q;

    bool p[8];
    #pragma unroll
    for (int i = 0; i < 8; i++) {
        const int t = t0 + i;
        const bool tmask = (t >= ts0 && t < te0) || (t >= ts1 && t < te1);
        p[i] = !(tmask || fmzero);
    }

    float4 v[8];
    #pragma unroll
    for (int i = 0; i < 8; i++) {
        v[i] = make_float4(0.f, 0.f, 0.f, 0.f);
        if (p[i]) v[i] = __ldcs(x + base + (size_t)i * 32);
    }

    #pragma unroll
    for (int i = 0; i < 8; i++) {
        float4 r;
        if (p[i]) {
            r.x = v[i].x * fm.x;
            r.y = v[i].y * fm.y;
            r.z = v[i].z * fm.z;
            r.w = v[i].w * fm.w;
        } else {
            r = make_float4(0.f, 0.f, 0.f, 0.f);
        }
        __stcs(out + base + (size_t)i * 32, r);
    }
}

extern "C" void kernel_launch(void* const* d_in, const int* in_sizes, int n_in,
                              void* d_out, int out_size) {
    const float* x     = (const float*)d_in[0];
    const int*   x_len = (const int*)d_in[1];
    float*       out   = (float*)d_out;

    const int B = in_sizes[1];                 // 128
    const int F = 128;                         // fixed by problem shape
    const int T = in_sizes[0] / (B * F);       // 4000

    dim3 grid(T / 32, B);                      // 125 x 128 blocks, one node
    specaug_fused_kernel<<<grid, 128>>>(
        (const float4*)x, (float4*)out, x_len, T);
    (void)n_in; (void)out_size; (void)F;
}

// round 5
// speedup vs baseline: 1.1022x; 1.0147x over previous
#include <cuda_runtime.h>
#include <cstdint>

// ---------------------------------------------------------------------------
// SpecAugment on GB300 — R5: R3's occupancy shape + R4's amortized hash.
//  * 256-thread block (8 warps), 4 float4 per thread -> regs ~30, occ ~80%.
//  * Warp 0 computes the 8 threefry hashes + mask intervals; smem broadcast.
//  * Streaming ld/st; loads predicated off where output is provably zero.
// B=128, T=4000, F=128.  Block covers 32 t-rows; grid=(125,128).
// ---------------------------------------------------------------------------

#define FREQ_MASK_SIZE 27.0f
#define TIME_MASK_PCT  0.25f

// ---- constexpr Threefry2x32 (20 rounds) for compile-time subkeys ----------
struct TFPair { unsigned a, b; };

constexpr unsigned rotl32c(unsigned x, int r) {
    return (x << r) | (x >> (32 - r));
}

constexpr TFPair threefry_const(unsigned k0, unsigned k1,
                                unsigned x0, unsigned x1) {
    unsigned ks2 = k0 ^ k1 ^ 0x1BD11BDAu;
    x0 += k0; x1 += k1;
    const int R[8] = {13, 15, 26, 6, 17, 29, 16, 24};
    for (int g = 0; g < 5; g++) {
        const int* r = (g % 2 == 0) ? R : R + 4;
        for (int i = 0; i < 4; i++) {
            x0 += x1; x1 = rotl32c(x1, r[i]); x1 ^= x0;
        }
        switch (g) {
            case 0: x0 += k1;  x1 += ks2 + 1u; break;
            case 1: x0 += ks2; x1 += k0 + 2u;  break;
            case 2: x0 += k0;  x1 += k1 + 3u;  break;
            case 3: x0 += k1;  x1 += ks2 + 4u; break;
            case 4: x0 += ks2; x1 += k0 + 5u;  break;
        }
    }
    return TFPair{x0, x1};
}

// split(key(42), 3), partitionable path: child i = threefry(key, (0, i))
constexpr TFPair KF = threefry_const(0u, 42u, 0u, 0u);
constexpr TFPair KV = threefry_const(0u, 42u, 0u, 1u);
constexpr TFPair KS = threefry_const(0u, 42u, 0u, 2u);

// ---- device Threefry2x32 (same schedule) ----------------------------------
__device__ __forceinline__ uint2 threefry2x32(unsigned k0, unsigned k1,
                                              unsigned x0, unsigned x1) {
    unsigned ks2 = k0 ^ k1 ^ 0x1BD11BDAu;
    x0 += k0; x1 += k1;
#define TF_RND(r) { x0 += x1; x1 = __funnelshift_l(x1, x1, (r)); x1 ^= x0; }
    TF_RND(13) TF_RND(15) TF_RND(26) TF_RND(6)
    x0 += k1;  x1 += ks2 + 1u;
    TF_RND(17) TF_RND(29) TF_RND(16) TF_RND(24)
    x0 += ks2; x1 += k0 + 2u;
    TF_RND(13) TF_RND(15) TF_RND(26) TF_RND(6)
    x0 += k0;  x1 += k1 + 3u;
    TF_RND(17) TF_RND(29) TF_RND(16) TF_RND(24)
    x0 += k1;  x1 += ks2 + 4u;
    TF_RND(13) TF_RND(15) TF_RND(26) TF_RND(6)
    x0 += ks2; x1 += k0 + 5u;
#undef TF_RND
    return make_uint2(x0, x1);
}

__device__ __forceinline__ float bits_to_unit(unsigned bits) {
    return __uint_as_float((bits >> 9) | 0x3F800000u) - 1.0f;
}

// ---------------------------------------------------------------------------
// Fused kernel. Block = 256 threads = 8 warps; warp w handles t-rows
// [blockIdx.x*32 + w*4, +4) with 32 float4 lanes over F=128. Grid=(T/32, B).
// ---------------------------------------------------------------------------
__global__ void __launch_bounds__(256)
specaug_fused_kernel(const float4* __restrict__ x,
                     float4* __restrict__ out,
                     const int* __restrict__ x_len,
                     int T) {
    __shared__ int s_m[8];   // fs0, fe0, fs1, fe1, ts0, te0, ts1, te1

    const int b = blockIdx.y;
    const int w = threadIdx.x >> 5;
    const int q = threadIdx.x & 31;

    // ---- warp 0: hashes + mask intervals, once per block -------------------
    if (w == 0) {
        const unsigned sel = (unsigned)q & 7u;
        unsigned k0, k1, j;
        if (sel < 4u)      { k0 = KF.a; k1 = KF.b; j = sel; }
        else if (sel < 6u) { k0 = KV.a; k1 = KV.b; j = 2u * (unsigned)b + (sel - 4u); }
        else               { k0 = KS.a; k1 = KS.b; j = 2u * (unsigned)b + (sel - 6u); }
        uint2 h = threefry2x32(k0, k1, 0u, j);
        float u = bits_to_unit(h.x ^ h.y);

        const unsigned FULL = 0xFFFFFFFFu;
        float u00 = __shfl_sync(FULL, u, 0);
        float u01 = __shfl_sync(FULL, u, 1);
        float u10 = __shfl_sync(FULL, u, 2);
        float u11 = __shfl_sync(FULL, u, 3);
        float uv0 = __shfl_sync(FULL, u, 4);
        float uv1 = __shfl_sync(FULL, u, 5);
        float us0 = __shfl_sync(FULL, u, 6);
        float us1 = __shfl_sync(FULL, u, 7);

        if (q == 0) {
            // frequency masks (fp32 ops matching the reference exactly);
            // floor results are exact small integers -> store as int.
            const float Ff = 128.0f;
            float fv0 = __fmul_rn(u00, FREQ_MASK_SIZE);
            float fb0 = __fmul_rn(u01, __fsub_rn(Ff, fv0));
            s_m[0] = (int)floorf(fb0);
            s_m[1] = (int)floorf(__fadd_rn(fb0, fv0));
            float fv1 = __fmul_rn(u10, FREQ_MASK_SIZE);
            float fb1 = __fmul_rn(u11, __fsub_rn(Ff, fv1));
            s_m[2] = (int)floorf(fb1);
            s_m[3] = (int)floorf(__fadd_rn(fb1, fv1));

            // adaptive time masks for batch b
            float xl = (float)__ldg(x_len + b);
            float tparam = floorf(__fmul_rn(TIME_MASK_PCT, xl));

            float tv0 = __fmul_rn(uv0, tparam);
            float tb0 = __fmul_rn(us0, __fsub_rn(xl, tv0));
            s_m[4] = (int)floorf(tb0);
            s_m[5] = (int)floorf(__fadd_rn(tb0, tv0));
            float tv1 = __fmul_rn(uv1, tparam);
            float tb1 = __fmul_rn(us1, __fsub_rn(xl, tv1));
            s_m[6] = (int)floorf(tb1);
            s_m[7] = (int)floorf(__fadd_rn(tb1, tv1));
        }
    }
    __syncthreads();

    const int fs0 = s_m[0], fe0 = s_m[1], fs1 = s_m[2], fe1 = s_m[3];
    const int ts0 = s_m[4], te0 = s_m[5], ts1 = s_m[6], te1 = s_m[7];

    // ---- per-lane frequency multiplier for bins 4q..4q+3 -------------------
    float4 fm;
    {
        const int f0 = 4 * q;
        const int f1 = f0 + 1, f2 = f0 + 2, f3 = f0 + 3;
        fm.x = ((f0 >= fs0 && f0 < fe0) || (f0 >= fs1 && f0 < fe1)) ? 0.f : 1.f;
        fm.y = ((f1 >= fs0 && f1 < fe0) || (f1 >= fs1 && f1 < fe1)) ? 0.f : 1.f;
        fm.z = ((f2 >= fs0 && f2 < fe0) || (f2 >= fs1 && f2 < fe1)) ? 0.f : 1.f;
        fm.w = ((f3 >= fs0 && f3 < fe0) || (f3 >= fs1 && f3 < fe1)) ? 0.f : 1.f;
    }
    const bool fmzero = (fm.x + fm.y + fm.z + fm.w) == 0.f;

    // ---- streaming apply: 4 rows per thread --------------------------------
    const int t0 = blockIdx.x * 32 + w * 4;
    const size_t base = ((size_t)b * T + t0) * 32 + q;

    bool p[4];
    #pragma unroll
    for (int i = 0; i < 4; i++) {
        const int t = t0 + i;
        const bool tmask = (t >= ts0 && t < te0) || (t >= ts1 && t < te1);
        p[i] = !(tmask || fmzero);
    }

    float4 v[4];
    #pragma unroll
    for (int i = 0; i < 4; i++) {
        v[i] = make_float4(0.f, 0.f, 0.f, 0.f);
        if (p[i]) v[i] = __ldcs(x + base + (size_t)i * 32);
    }

    #pragma unroll
    for (int i = 0; i < 4; i++) {
        float4 r;
        if (p[i]) {
            r.x = v[i].x * fm.x;
            r.y = v[i].y * fm.y;
            r.z = v[i].z * fm.z;
            r.w = v[i].w * fm.w;
        } else {
            r = make_float4(0.f, 0.f, 0.f, 0.f);
        }
        __stcs(out + base + (size_t)i * 32, r);
    }
}

extern "C" void kernel_launch(void* const* d_in, const int* in_sizes, int n_in,
                              void* d_out, int out_size) {
    const float* x     = (const float*)d_in[0];
    const int*   x_len = (const int*)d_in[1];
    float*       out   = (float*)d_out;

    const int B = in_sizes[1];                 // 128
    const int F = 128;                         // fixed by problem shape
    const int T = in_sizes[0] / (B * F);       // 4000

    dim3 grid(T / 32, B);                      // 125 x 128 blocks, one node
    specaug_fused_kernel<<<grid, 256>>>(
        (const float4*)x, (float4*)out, x_len, T);
    (void)n_in; (void)out_size; (void)F;
}